// round 1
// baseline (speedup 1.0000x reference)
#include <cuda_runtime.h>
#include <cstdint>

// Problem constants (fixed by the dataset)
#define N_NODES 100000
#define N_EDGES 3200000
#define D_FEAT  128

// ---------------- static scratch (no allocations allowed) ----------------
__device__ int  g_count[N_NODES];        // per-row edge counts
__device__ int  g_rowstart[N_NODES + 1]; // CSR row offsets (exclusive scan)
__device__ int  g_cursor[N_NODES];       // scatter cursors
__device__ int2 g_edges[N_EDGES];        // row-sorted {col, val_bits}

#define SCAN_T 1024
#define NB ((N_NODES + SCAN_T - 1) / SCAN_T)   // 98
__device__ int g_blocksums[NB];
__device__ int g_blockoff[NB];

// ---------------- phase 0: zero counters ----------------
__global__ void k_zero() {
    int i = blockIdx.x * blockDim.x + threadIdx.x;
    if (i < N_NODES) g_count[i] = 0;
}

// ---------------- phase 1: histogram of rows ----------------
__global__ void k_hist(const int* __restrict__ rows) {
    int e = blockIdx.x * blockDim.x + threadIdx.x;
    if (e < N_EDGES) atomicAdd(&g_count[rows[e]], 1);
}

// ---------------- phase 2a: per-block exclusive scan ----------------
__global__ void k_scan1() {
    __shared__ int s[SCAN_T];
    int t = threadIdx.x;
    int gid = blockIdx.x * SCAN_T + t;
    int v = (gid < N_NODES) ? g_count[gid] : 0;
    s[t] = v;
    __syncthreads();
    #pragma unroll
    for (int off = 1; off < SCAN_T; off <<= 1) {
        int add = (t >= off) ? s[t - off] : 0;
        __syncthreads();
        s[t] += add;
        __syncthreads();
    }
    if (gid < N_NODES) g_rowstart[gid] = s[t] - v;   // exclusive within block
    if (t == SCAN_T - 1) g_blocksums[blockIdx.x] = s[t];
}

// ---------------- phase 2b: scan the 98 block sums ----------------
__global__ void k_scan2() {
    __shared__ int s[128];
    int t = threadIdx.x;
    int v = (t < NB) ? g_blocksums[t] : 0;
    s[t] = v;
    __syncthreads();
    #pragma unroll
    for (int off = 1; off < 128; off <<= 1) {
        int add = (t >= off) ? s[t - off] : 0;
        __syncthreads();
        s[t] += add;
        __syncthreads();
    }
    if (t < NB) g_blockoff[t] = s[t] - v;
}

// ---------------- phase 2c: apply block offsets, init cursors ----------------
__global__ void k_scan3() {
    int i = blockIdx.x * blockDim.x + threadIdx.x;
    if (i < N_NODES) {
        int rs = g_rowstart[i] + g_blockoff[i >> 10];
        g_rowstart[i] = rs;
        g_cursor[i]   = rs;
    }
    if (i == 0) g_rowstart[N_NODES] = N_EDGES;
}

// ---------------- phase 3: scatter edges into row-sorted order ----------------
__global__ void k_scatter(const int* __restrict__ rows,
                          const int* __restrict__ cols,
                          const float* __restrict__ vals) {
    int e = blockIdx.x * blockDim.x + threadIdx.x;
    if (e < N_EDGES) {
        int r = rows[e];
        int pos = atomicAdd(&g_cursor[r], 1);
        g_edges[pos] = make_int2(cols[e], __float_as_int(vals[e]));
    }
}

// ---------------- phase 4: warp-per-row gather + accumulate ----------------
__global__ void __launch_bounds__(256)
k_gather(const float* __restrict__ embeds, float* __restrict__ out) {
    int warp = (blockIdx.x * blockDim.x + threadIdx.x) >> 5;
    int lane = threadIdx.x & 31;
    if (warp >= N_NODES) return;

    int start = g_rowstart[warp];
    int end   = g_rowstart[warp + 1];

    const float4* __restrict__ emb4 = (const float4*)embeds;
    float4 acc = make_float4(0.f, 0.f, 0.f, 0.f);

    int e = start;
    // unroll by 4 for memory-level parallelism
    for (; e + 4 <= end; e += 4) {
        int2 e0 = g_edges[e + 0];
        int2 e1 = g_edges[e + 1];
        int2 e2 = g_edges[e + 2];
        int2 e3 = g_edges[e + 3];
        float4 m0 = emb4[e0.x * 32 + lane];
        float4 m1 = emb4[e1.x * 32 + lane];
        float4 m2 = emb4[e2.x * 32 + lane];
        float4 m3 = emb4[e3.x * 32 + lane];
        float v0 = __int_as_float(e0.y);
        float v1 = __int_as_float(e1.y);
        float v2 = __int_as_float(e2.y);
        float v3 = __int_as_float(e3.y);
        acc.x = fmaf(v0, m0.x, acc.x); acc.y = fmaf(v0, m0.y, acc.y);
        acc.z = fmaf(v0, m0.z, acc.z); acc.w = fmaf(v0, m0.w, acc.w);
        acc.x = fmaf(v1, m1.x, acc.x); acc.y = fmaf(v1, m1.y, acc.y);
        acc.z = fmaf(v1, m1.z, acc.z); acc.w = fmaf(v1, m1.w, acc.w);
        acc.x = fmaf(v2, m2.x, acc.x); acc.y = fmaf(v2, m2.y, acc.y);
        acc.z = fmaf(v2, m2.z, acc.z); acc.w = fmaf(v2, m2.w, acc.w);
        acc.x = fmaf(v3, m3.x, acc.x); acc.y = fmaf(v3, m3.y, acc.y);
        acc.z = fmaf(v3, m3.z, acc.z); acc.w = fmaf(v3, m3.w, acc.w);
    }
    for (; e < end; e++) {
        int2 ed = g_edges[e];
        float4 m = emb4[ed.x * 32 + lane];
        float v = __int_as_float(ed.y);
        acc.x = fmaf(v, m.x, acc.x); acc.y = fmaf(v, m.y, acc.y);
        acc.z = fmaf(v, m.z, acc.z); acc.w = fmaf(v, m.w, acc.w);
    }

    ((float4*)out)[warp * 32 + lane] = acc;
}

// ---------------- launch ----------------
extern "C" void kernel_launch(void* const* d_in, const int* in_sizes, int n_in,
                              void* d_out, int out_size) {
    const int*   rows   = (const int*)d_in[0];
    const int*   cols   = (const int*)d_in[1];
    const float* vals   = (const float*)d_in[2];
    const float* embeds = (const float*)d_in[3];
    float*       out    = (float*)d_out;

    const int TB = 256;
    k_zero<<<(N_NODES + TB - 1) / TB, TB>>>();
    k_hist<<<(N_EDGES + TB - 1) / TB, TB>>>(rows);
    k_scan1<<<NB, SCAN_T>>>();
    k_scan2<<<1, 128>>>();
    k_scan3<<<(N_NODES + TB - 1) / TB, TB>>>();
    k_scatter<<<(N_EDGES + TB - 1) / TB, TB>>>(rows, cols, vals);
    k_gather<<<(N_NODES * 32 + TB - 1) / TB, TB>>>(embeds, out);
}

// round 2
// speedup vs baseline: 1.0019x; 1.0019x over previous
#include <cuda_runtime.h>
#include <cstdint>

// Problem constants (fixed by the dataset)
#define N_NODES 100000
#define N_EDGES 3200000
#define D_FEAT  128

// ---------------- static scratch (no allocations allowed) ----------------
__device__ int  g_count[N_NODES];        // per-row edge counts
__device__ int  g_rowstart[N_NODES + 1]; // CSR row offsets (exclusive scan)
__device__ int  g_cursor[N_NODES];       // scatter cursors
__device__ int2 g_edges[N_EDGES];        // row-sorted {col, val_bits}

#define SCAN_T 1024
#define NB ((N_NODES + SCAN_T - 1) / SCAN_T)   // 98
__device__ int g_blocksums[NB];
__device__ int g_blockoff[NB];

// ---------------- phase 1: histogram of rows ----------------
__global__ void k_hist(const int* __restrict__ rows) {
    int e = blockIdx.x * blockDim.x + threadIdx.x;
    if (e < N_EDGES) atomicAdd(&g_count[__ldcs(&rows[e])], 1);
}

// ---------------- phase 2a: per-block exclusive scan ----------------
__global__ void k_scan1() {
    __shared__ int s[SCAN_T];
    int t = threadIdx.x;
    int gid = blockIdx.x * SCAN_T + t;
    int v = (gid < N_NODES) ? g_count[gid] : 0;
    s[t] = v;
    __syncthreads();
    #pragma unroll
    for (int off = 1; off < SCAN_T; off <<= 1) {
        int add = (t >= off) ? s[t - off] : 0;
        __syncthreads();
        s[t] += add;
        __syncthreads();
    }
    if (gid < N_NODES) g_rowstart[gid] = s[t] - v;   // exclusive within block
    if (t == SCAN_T - 1) g_blocksums[blockIdx.x] = s[t];
}

// ---------------- phase 2b: scan the 98 block sums ----------------
__global__ void k_scan2() {
    __shared__ int s[128];
    int t = threadIdx.x;
    int v = (t < NB) ? g_blocksums[t] : 0;
    s[t] = v;
    __syncthreads();
    #pragma unroll
    for (int off = 1; off < 128; off <<= 1) {
        int add = (t >= off) ? s[t - off] : 0;
        __syncthreads();
        s[t] += add;
        __syncthreads();
    }
    if (t < NB) g_blockoff[t] = s[t] - v;
}

// ---------------- phase 2c: apply block offsets, init cursors ----------------
__global__ void k_scan3() {
    int i = blockIdx.x * blockDim.x + threadIdx.x;
    if (i < N_NODES) {
        int rs = g_rowstart[i] + g_blockoff[i >> 10];
        g_rowstart[i] = rs;
        g_cursor[i]   = rs;
    }
    if (i == 0) g_rowstart[N_NODES] = N_EDGES;
}

// ---------------- phase 3: scatter edges into row-sorted order ----------------
// g_edges writes stay evict-normal: they are read exactly once by k_gather
// immediately after, so letting them live in L2 saves an HBM round-trip.
__global__ void k_scatter(const int* __restrict__ rows,
                          const int* __restrict__ cols,
                          const float* __restrict__ vals) {
    int e = blockIdx.x * blockDim.x + threadIdx.x;
    if (e < N_EDGES) {
        int r = __ldcs(&rows[e]);
        int pos = atomicAdd(&g_cursor[r], 1);
        g_edges[pos] = make_int2(__ldcs(&cols[e]), __float_as_int(__ldcs(&vals[e])));
    }
}

// ---------------- phase 4: warp-per-row gather + accumulate ----------------
// Edge reads use __ldcs (read-once, evict-first) and out writes use __stcs
// (write-once, never re-read) so that embeds (51 MB) keeps maximum L2
// residency against the ~77 MB of streaming traffic.
__global__ void __launch_bounds__(256)
k_gather(const float* __restrict__ embeds, float* __restrict__ out) {
    int warp = (blockIdx.x * blockDim.x + threadIdx.x) >> 5;
    int lane = threadIdx.x & 31;
    if (warp >= N_NODES) return;

    int start = g_rowstart[warp];
    int end   = g_rowstart[warp + 1];

    const float4* __restrict__ emb4 = (const float4*)embeds;
    float4 acc = make_float4(0.f, 0.f, 0.f, 0.f);

    int e = start;
    // unroll by 4 for memory-level parallelism
    for (; e + 4 <= end; e += 4) {
        int2 e0 = __ldcs(&g_edges[e + 0]);
        int2 e1 = __ldcs(&g_edges[e + 1]);
        int2 e2 = __ldcs(&g_edges[e + 2]);
        int2 e3 = __ldcs(&g_edges[e + 3]);
        float4 m0 = emb4[e0.x * 32 + lane];
        float4 m1 = emb4[e1.x * 32 + lane];
        float4 m2 = emb4[e2.x * 32 + lane];
        float4 m3 = emb4[e3.x * 32 + lane];
        float v0 = __int_as_float(e0.y);
        float v1 = __int_as_float(e1.y);
        float v2 = __int_as_float(e2.y);
        float v3 = __int_as_float(e3.y);
        acc.x = fmaf(v0, m0.x, acc.x); acc.y = fmaf(v0, m0.y, acc.y);
        acc.z = fmaf(v0, m0.z, acc.z); acc.w = fmaf(v0, m0.w, acc.w);
        acc.x = fmaf(v1, m1.x, acc.x); acc.y = fmaf(v1, m1.y, acc.y);
        acc.z = fmaf(v1, m1.z, acc.z); acc.w = fmaf(v1, m1.w, acc.w);
        acc.x = fmaf(v2, m2.x, acc.x); acc.y = fmaf(v2, m2.y, acc.y);
        acc.z = fmaf(v2, m2.z, acc.z); acc.w = fmaf(v2, m2.w, acc.w);
        acc.x = fmaf(v3, m3.x, acc.x); acc.y = fmaf(v3, m3.y, acc.y);
        acc.z = fmaf(v3, m3.z, acc.z); acc.w = fmaf(v3, m3.w, acc.w);
    }
    for (; e < end; e++) {
        int2 ed = __ldcs(&g_edges[e]);
        float4 m = emb4[ed.x * 32 + lane];
        float v = __int_as_float(ed.y);
        acc.x = fmaf(v, m.x, acc.x); acc.y = fmaf(v, m.y, acc.y);
        acc.z = fmaf(v, m.z, acc.z); acc.w = fmaf(v, m.w, acc.w);
    }

    __stcs(&((float4*)out)[warp * 32 + lane], acc);
}

// ---------------- launch ----------------
extern "C" void kernel_launch(void* const* d_in, const int* in_sizes, int n_in,
                              void* d_out, int out_size) {
    const int*   rows   = (const int*)d_in[0];
    const int*   cols   = (const int*)d_in[1];
    const float* vals   = (const float*)d_in[2];
    const float* embeds = (const float*)d_in[3];
    float*       out    = (float*)d_out;

    // zero the histogram counters via capturable async memset (saves a launch)
    void* count_ptr = nullptr;
    cudaGetSymbolAddress(&count_ptr, g_count);
    cudaMemsetAsync(count_ptr, 0, N_NODES * sizeof(int));

    const int TB = 256;
    k_hist<<<(N_EDGES + TB - 1) / TB, TB>>>(rows);
    k_scan1<<<NB, SCAN_T>>>();
    k_scan2<<<1, 128>>>();
    k_scan3<<<(N_NODES + TB - 1) / TB, TB>>>();
    k_scatter<<<(N_EDGES + TB - 1) / TB, TB>>>(rows, cols, vals);
    k_gather<<<(N_NODES * 32 + TB - 1) / TB, TB>>>(embeds, out);
}